// round 6
// baseline (speedup 1.0000x reference)
#include <cuda_runtime.h>

// ---------------------------------------------------------------------------
// SINDy autoencoder forward (batch-1, HBM-bound, ~545MB weights/call).
// Output: [z(16) | dz(16) | dzb(16) | xb(16384) | dxb(16384)] = 32816 f32
// R6: R4 structure (5 kernels, PDL-chained) + forced 6 blocks/SM on the two
//     256MB kernels (launch_bounds minBlocks) to raise DRAM 74% -> ~85%.
// ---------------------------------------------------------------------------

#define W0_OUT 4096
#define W0_IN  16384
#define W1_OUT 1024
#define LATENT 16
#define SINDY_DIM 984

__device__ float g_pre1[W0_OUT], g_u1[W0_OUT];
__device__ float g_pre2p[2 * W1_OUT], g_u2p[2 * W1_OUT];
__device__ float g_g1[1024],  g_p1[1024];
__device__ float g_q2[4096],  g_v2[4096];

__device__ __forceinline__ float sigf(float x) { return 1.0f / (1.0f + __expf(-x)); }
__device__ __forceinline__ float4 ldcs4(const float* p) { return __ldcs((const float4*)p); }

__device__ __forceinline__ void pdl_trigger() {
    asm volatile("griddepcontrol.launch_dependents;" ::: "memory");
}
__device__ __forceinline__ void pdl_wait() {
    asm volatile("griddepcontrol.wait;" ::: "memory");
}
__device__ __forceinline__ void l2_prefetch(const void* p) {
    asm volatile("prefetch.global.L2 [%0];" :: "l"(p));
}
template<int THREADS>
__device__ __forceinline__ void prefetch_tile(const float* base, int bytes) {
    const char* p = (const char*)base;
    for (int off = threadIdx.x * 128; off < bytes; off += THREADS * 128)
        l2_prefetch(p + off);
}

// ---------------------------------------------------------------------------
// Dual matvec over a K-chunk: outA[row]=W@a(+bias), outB[row]=W@b.
// ---------------------------------------------------------------------------
template<int KSTRIDE, int KCHUNK, int ROWS, int THREADS, bool SIG>
__device__ __forceinline__ void dual_body(
    const float* __restrict__ W,
    const float* __restrict__ av,
    const float* __restrict__ bv,
    const float* __restrict__ bias,
    float* __restrict__ outA,
    float* __restrict__ outB,
    int row0)
{
    constexpr int NW = THREADS / 32;
    constexpr int ITERS = KCHUNK / (THREADS * 4);
    const int tid = threadIdx.x;

    float accA[ROWS], accB[ROWS];
#pragma unroll
    for (int r = 0; r < ROWS; r++) { accA[r] = 0.0f; accB[r] = 0.0f; }

#pragma unroll 2
    for (int it = 0; it < ITERS; it++) {
        const int k = (it * THREADS + tid) * 4;
        float4 w4[ROWS];
#pragma unroll
        for (int r = 0; r < ROWS; r++)
            w4[r] = ldcs4(W + (size_t)r * KSTRIDE + k);
        float4 a4 = *(const float4*)(av + k);
        float4 b4 = *(const float4*)(bv + k);
        if (SIG) {
            float s;
            s = sigf(a4.x); b4.x *= s * (1.0f - s); a4.x = s;
            s = sigf(a4.y); b4.y *= s * (1.0f - s); a4.y = s;
            s = sigf(a4.z); b4.z *= s * (1.0f - s); a4.z = s;
            s = sigf(a4.w); b4.w *= s * (1.0f - s); a4.w = s;
        }
#pragma unroll
        for (int r = 0; r < ROWS; r++) {
            accA[r] = fmaf(w4[r].x, a4.x, accA[r]);
            accA[r] = fmaf(w4[r].y, a4.y, accA[r]);
            accA[r] = fmaf(w4[r].z, a4.z, accA[r]);
            accA[r] = fmaf(w4[r].w, a4.w, accA[r]);
            accB[r] = fmaf(w4[r].x, b4.x, accB[r]);
            accB[r] = fmaf(w4[r].y, b4.y, accB[r]);
            accB[r] = fmaf(w4[r].z, b4.z, accB[r]);
            accB[r] = fmaf(w4[r].w, b4.w, accB[r]);
        }
    }

    __shared__ float sA[NW][ROWS], sB[NW][ROWS];
    const int lane = tid & 31, warp = tid >> 5;
#pragma unroll
    for (int r = 0; r < ROWS; r++) {
        float vA = accA[r], vB = accB[r];
#pragma unroll
        for (int o = 16; o; o >>= 1) {
            vA += __shfl_xor_sync(0xffffffffu, vA, o);
            vB += __shfl_xor_sync(0xffffffffu, vB, o);
        }
        if (lane == 0) { sA[warp][r] = vA; sB[warp][r] = vB; }
    }
    __syncthreads();
    if (tid < ROWS) {
        float vA = 0.0f, vB = 0.0f;
#pragma unroll
        for (int w = 0; w < NW; w++) { vA += sA[w][tid]; vB += sB[w][tid]; }
        if (bias) vA += bias[row0 + tid];
        outA[row0 + tid] = vA;
        outB[row0 + tid] = vB;
    }
}

// enc L0 (256 MB, first in chain). Force 6 blocks/SM.
__global__ void __launch_bounds__(256, 6) k_enc0(
    const float* __restrict__ W, const float* __restrict__ x,
    const float* __restrict__ dx, const float* __restrict__ b)
{
    pdl_trigger();
    const int row0 = blockIdx.x * 4;
    dual_body<W0_IN, W0_IN, 4, 256, false>(
        W + (size_t)row0 * W0_IN, x, dx, b, g_pre1, g_u1, row0);
}

// enc L1, split-K x2 (16 MB)
__global__ void __launch_bounds__(256) k_enc1(
    const float* __restrict__ W, const float* __restrict__ b)
{
    pdl_trigger();
    const int row0  = blockIdx.x * 4;
    const int split = blockIdx.y;
    const int koff  = split * 2048;
    const float* Wt = W + (size_t)row0 * W0_OUT + koff;
#pragma unroll
    for (int r = 0; r < 4; r++)
        prefetch_tile<256>(Wt + (size_t)r * W0_OUT, 8192);
    pdl_wait();
    dual_body<W0_OUT, 2048, 4, 256, true>(
        Wt, g_pre1 + koff, g_u1 + koff,
        split == 0 ? b : nullptr,
        g_pre2p + split * W1_OUT, g_u2p + split * W1_OUT, row0);
}

// dec L1 (16 MB)
__global__ void __launch_bounds__(256) k_dec1(
    const float* __restrict__ W, const float* __restrict__ b)
{
    pdl_trigger();
    const int row0 = blockIdx.x * 4;
    const float* Wt = W + (size_t)row0 * 1024;
    prefetch_tile<256>(Wt, 4 * 1024 * 4);
    pdl_wait();
    dual_body<1024, 1024, 4, 256, false>(
        Wt, g_g1, g_p1, b, g_q2, g_v2, row0);
}

// dec L2 (256 MB, last). Force 6 blocks/SM.
__global__ void __launch_bounds__(256, 6) k_dec2(
    const float* __restrict__ W, const float* __restrict__ b,
    float* __restrict__ out)
{
    const int row0 = blockIdx.x * 4;
    const float* Wt = W + (size_t)row0 * 4096;
    prefetch_tile<256>(Wt, 4 * 4096 * 4);
    pdl_wait();
    dual_body<4096, 4096, 4, 256, true>(
        Wt, g_q2, g_v2, b, out + 48, out + 48 + 16384, row0);
}

// ---------------------------------------------------------------------------
// Middle chain, one block, 512 threads, weights prefetched to smem.
// ---------------------------------------------------------------------------
#define SM_WE2   0
#define SM_EW    16384
#define SM_WD0   32128
#define SM_H2    48512
#define SM_T2    49536
#define SM_THETA 50560
#define SM_FLOATS 51544
#define SM_BYTES (SM_FLOATS * 4)

__global__ void __launch_bounds__(512) k_small(
    const float* __restrict__ we_w2, const float* __restrict__ we_b2,
    const float* __restrict__ E_w,   const float* __restrict__ E_b,
    const float* __restrict__ wd_w0, const float* __restrict__ wd_b0,
    float* __restrict__ out)
{
    extern __shared__ float sm[];
    __shared__ float z[LATENT], dz[LATENT], dzb[LATENT];

    const int tid = threadIdx.x;
    const int lane = tid & 31, wid = tid >> 5;

    pdl_trigger();
    prefetch_tile<512>(we_w2, 16384 * 4);
    prefetch_tile<512>(E_w,   15744 * 4);
    prefetch_tile<512>(wd_w0, 16384 * 4);
    pdl_wait();

    for (int i = tid; i < 4096; i += 512)
        *(float4*)(sm + SM_WE2 + i * 4) = ldcs4(we_w2 + i * 4);
    for (int i = tid; i < 3936; i += 512)
        *(float4*)(sm + SM_EW + i * 4) = ldcs4(E_w + i * 4);
    for (int i = tid; i < 4096; i += 512)
        *(float4*)(sm + SM_WD0 + i * 4) = ldcs4(wd_w0 + i * 4);
    for (int i = tid; i < W1_OUT; i += 512) {
        float pre = g_pre2p[i] + g_pre2p[W1_OUT + i];
        float u   = g_u2p[i]   + g_u2p[W1_OUT + i];
        float s = sigf(pre);
        sm[SM_H2 + i] = s;
        sm[SM_T2 + i] = s * (1.0f - s) * u;
    }
    __syncthreads();

    {
        float az = 0.0f, ad = 0.0f;
        const float* wr = sm + SM_WE2 + wid * W1_OUT;
        for (int c = lane; c < W1_OUT; c += 32) {
            float w = wr[c];
            az = fmaf(w, sm[SM_H2 + c], az);
            ad = fmaf(w, sm[SM_T2 + c], ad);
        }
#pragma unroll
        for (int o = 16; o; o >>= 1) {
            az += __shfl_xor_sync(0xffffffffu, az, o);
            ad += __shfl_xor_sync(0xffffffffu, ad, o);
        }
        if (lane == 0) { z[wid] = az + we_b2[wid]; dz[wid] = ad; }
    }
    __syncthreads();

    if (tid < LATENT) { out[tid] = z[tid]; out[LATENT + tid] = dz[tid]; }

    for (int idx = tid; idx < SINDY_DIM; idx += 512) {
        float v;
        if (idx < 16) v = 1.0f;
        else if (idx < 32) v = z[idx - 16];
        else if (idx < 168) {
            int q = idx - 32, i = 0;
            for (;;) { int m = 16 - i; if (q < m) break; q -= m; i++; }
            v = z[i] * z[i + q];
        } else {
            int t = idx - 168, i = 0;
            for (;;) { int m = 16 - i; int c = m * (m + 1) / 2; if (t < c) break; t -= c; i++; }
            int j = i;
            for (;;) { int m = 16 - j; if (t < m) break; t -= m; j++; }
            v = z[i] * z[j] * z[j + t];
        }
        sm[SM_THETA + idx] = v;
    }
    __syncthreads();

    {
        float a = 0.0f;
        const float* er = sm + SM_EW + wid * SINDY_DIM;
        for (int c = lane; c < SINDY_DIM; c += 32)
            a = fmaf(er[c], sm[SM_THETA + c], a);
#pragma unroll
        for (int o = 16; o; o >>= 1)
            a += __shfl_xor_sync(0xffffffffu, a, o);
        if (lane == 0) dzb[wid] = a + E_b[wid];
    }
    __syncthreads();

    if (tid < LATENT) out[32 + tid] = dzb[tid];

    for (int row = tid; row < 1024; row += 512) {
        float a = wd_b0[row], bb = 0.0f;
        const float* wr = sm + SM_WD0 + row * LATENT;
#pragma unroll
        for (int c = 0; c < LATENT; c++) {
            float w = wr[c];
            a  = fmaf(w, z[c],   a);
            bb = fmaf(w, dzb[c], bb);
        }
        float s = sigf(a);
        g_g1[row] = s;
        g_p1[row] = s * (1.0f - s) * bb;
    }
}

// ---------------------------------------------------------------------------
extern "C" void kernel_launch(void* const* d_in, const int* in_sizes, int n_in,
                              void* d_out, int out_size)
{
    const float* x     = (const float*)d_in[0];
    const float* dx    = (const float*)d_in[1];
    const float* we_w0 = (const float*)d_in[3];
    const float* we_b0 = (const float*)d_in[4];
    const float* we_w1 = (const float*)d_in[5];
    const float* we_b1 = (const float*)d_in[6];
    const float* we_w2 = (const float*)d_in[7];
    const float* we_b2 = (const float*)d_in[8];
    const float* wd_w0 = (const float*)d_in[9];
    const float* wd_b0 = (const float*)d_in[10];
    const float* wd_w1 = (const float*)d_in[11];
    const float* wd_b1 = (const float*)d_in[12];
    const float* wd_w2 = (const float*)d_in[13];
    const float* wd_b2 = (const float*)d_in[14];
    const float* E_w   = (const float*)d_in[15];
    const float* E_b   = (const float*)d_in[16];
    float* out = (float*)d_out;

    cudaFuncSetAttribute(k_small, cudaFuncAttributeMaxDynamicSharedMemorySize, SM_BYTES);

    cudaLaunchAttribute attr[1];
    attr[0].id = cudaLaunchAttributeProgrammaticStreamSerialization;
    attr[0].val.programmaticStreamSerializationAllowed = 1;

    cudaLaunchConfig_t cfg{};
    cfg.blockDim = dim3(256, 1, 1);
    cfg.dynamicSmemBytes = 0;
    cfg.stream = 0;
    cfg.attrs = attr;
    cfg.numAttrs = 1;

    // 1) enc L0 (256 MB)
    cfg.gridDim = dim3(W0_OUT / 4, 1, 1);
    cudaLaunchKernelEx(&cfg, k_enc0, we_w0, x, dx, we_b0);

    // 2) enc L1 (16 MB, split-K x2)
    cfg.gridDim = dim3(W1_OUT / 4, 2, 1);
    cudaLaunchKernelEx(&cfg, k_enc1, we_w1, we_b1);

    // 3) middle chain
    {
        cudaLaunchConfig_t cs = cfg;
        cs.gridDim = dim3(1, 1, 1);
        cs.blockDim = dim3(512, 1, 1);
        cs.dynamicSmemBytes = SM_BYTES;
        cudaLaunchKernelEx(&cs, k_small, we_w2, we_b2, E_w, E_b, wd_w0, wd_b0, out);
    }

    // 4) dec L1 (16 MB)
    cfg.gridDim = dim3(4096 / 4, 1, 1);
    cudaLaunchKernelEx(&cfg, k_dec1, wd_w1, wd_b1);

    // 5) dec L2 (256 MB)
    cfg.gridDim = dim3(16384 / 4, 1, 1);
    cudaLaunchKernelEx(&cfg, k_dec2, wd_w2, wd_b2, out);
}

// round 7
// speedup vs baseline: 1.2392x; 1.2392x over previous
#include <cuda_runtime.h>

// ---------------------------------------------------------------------------
// SINDy autoencoder forward (batch-1, HBM-bound, ~545MB weights/call).
// Output: [z(16) | dz(16) | dzb(16) | xb(16384) | dxb(16384)] = 32816 f32
// R7: R4 structure; big kernels rewritten as per-thread cp.async 2-stage
//     pipelines (MLP decoupled from registers, no syncthreads in mainloop).
// ---------------------------------------------------------------------------

#define W0_OUT 4096
#define W0_IN  16384
#define W1_OUT 1024
#define LATENT 16
#define SINDY_DIM 984

__device__ float g_pre1[W0_OUT], g_u1[W0_OUT];
__device__ float g_pre2p[2 * W1_OUT], g_u2p[2 * W1_OUT];
__device__ float g_g1[1024],  g_p1[1024];
__device__ float g_q2[4096],  g_v2[4096];

__device__ __forceinline__ float sigf(float x) { return 1.0f / (1.0f + __expf(-x)); }
__device__ __forceinline__ float4 ldcs4(const float* p) { return __ldcs((const float4*)p); }

__device__ __forceinline__ void pdl_trigger() {
    asm volatile("griddepcontrol.launch_dependents;" ::: "memory");
}
__device__ __forceinline__ void pdl_wait() {
    asm volatile("griddepcontrol.wait;" ::: "memory");
}
__device__ __forceinline__ void l2_prefetch(const void* p) {
    asm volatile("prefetch.global.L2 [%0];" :: "l"(p));
}
template<int THREADS>
__device__ __forceinline__ void prefetch_tile(const float* base, int bytes) {
    const char* p = (const char*)base;
    for (int off = threadIdx.x * 128; off < bytes; off += THREADS * 128)
        l2_prefetch(p + off);
}

__device__ __forceinline__ unsigned smem_u32(const void* p) {
    return (unsigned)__cvta_generic_to_shared(p);
}
__device__ __forceinline__ void cp16(unsigned dst, const float* src) {
    asm volatile("cp.async.cg.shared.global [%0], [%1], 16;" :: "r"(dst), "l"(src));
}
__device__ __forceinline__ void cp_commit() {
    asm volatile("cp.async.commit_group;");
}
__device__ __forceinline__ void cp_wait1() {
    asm volatile("cp.async.wait_group 1;");
}

// ---------------------------------------------------------------------------
// Big dual matvec, cp.async 2-stage pipeline.
// ROWS=4, THREADS=256, CHUNK=1024 cols/stage.
// Each thread stages and consumes ONLY its own 16B slices -> no __syncthreads
// in the mainloop (cp.async groups are per-thread).
// Dyn smem: weights 2*4*1024 + acts 2*2*1024 floats = 48KB.
// ---------------------------------------------------------------------------
#define BIG_SM_FLOATS (2*4*1024 + 2*2*1024)
#define BIG_SM_BYTES  (BIG_SM_FLOATS * 4)

template<int K, bool SIG>
__device__ __forceinline__ void big_body(
    const float* __restrict__ W,      // block's 4-row tile base
    const float* __restrict__ av,
    const float* __restrict__ bv,
    const float* __restrict__ bias,
    float* __restrict__ outA,
    float* __restrict__ outB,
    int row0)
{
    constexpr int CHUNK = 1024;
    constexpr int NC = K / CHUNK;
    extern __shared__ float sm[];
    float* smw = sm;                   // [2][4][1024]
    float* sma = sm + 8192;            // [2][1024]
    float* smb = sm + 8192 + 2048;     // [2][1024]

    const int tid = threadIdx.x;
    const int t4  = tid * 4;

    auto load_stage = [&](int c, int buf) {
        const int col = c * CHUNK + t4;
#pragma unroll
        for (int r = 0; r < 4; r++)
            cp16(smem_u32(smw + (buf * 4 + r) * CHUNK + t4), W + (size_t)r * K + col);
        cp16(smem_u32(sma + buf * CHUNK + t4), av + col);
        cp16(smem_u32(smb + buf * CHUNK + t4), bv + col);
        cp_commit();
    };

    load_stage(0, 0);
    load_stage(1, 1);

    float accA[4] = {0.f, 0.f, 0.f, 0.f};
    float accB[4] = {0.f, 0.f, 0.f, 0.f};

    for (int c = 0; c < NC; c++) {
        cp_wait1();                       // chunk c's group complete (per-thread)
        const int buf = c & 1;
        float4 a4 = *(const float4*)(sma + buf * CHUNK + t4);
        float4 b4 = *(const float4*)(smb + buf * CHUNK + t4);
        if (SIG) {
            float s;
            s = sigf(a4.x); b4.x *= s * (1.0f - s); a4.x = s;
            s = sigf(a4.y); b4.y *= s * (1.0f - s); a4.y = s;
            s = sigf(a4.z); b4.z *= s * (1.0f - s); a4.z = s;
            s = sigf(a4.w); b4.w *= s * (1.0f - s); a4.w = s;
        }
#pragma unroll
        for (int r = 0; r < 4; r++) {
            const float4 w4 = *(const float4*)(smw + (buf * 4 + r) * CHUNK + t4);
            accA[r] = fmaf(w4.x, a4.x, accA[r]);
            accA[r] = fmaf(w4.y, a4.y, accA[r]);
            accA[r] = fmaf(w4.z, a4.z, accA[r]);
            accA[r] = fmaf(w4.w, a4.w, accA[r]);
            accB[r] = fmaf(w4.x, b4.x, accB[r]);
            accB[r] = fmaf(w4.y, b4.y, accB[r]);
            accB[r] = fmaf(w4.z, b4.z, accB[r]);
            accB[r] = fmaf(w4.w, b4.w, accB[r]);
        }
        if (c + 2 < NC) load_stage(c + 2, buf);
        else cp_commit();                 // keep group accounting uniform
    }

    // cross-warp reduction (8 warps)
    __shared__ float sA[8][4], sB[8][4];
    const int lane = tid & 31, warp = tid >> 5;
#pragma unroll
    for (int r = 0; r < 4; r++) {
        float vA = accA[r], vB = accB[r];
#pragma unroll
        for (int o = 16; o; o >>= 1) {
            vA += __shfl_xor_sync(0xffffffffu, vA, o);
            vB += __shfl_xor_sync(0xffffffffu, vB, o);
        }
        if (lane == 0) { sA[warp][r] = vA; sB[warp][r] = vB; }
    }
    __syncthreads();
    if (tid < 4) {
        float vA = 0.0f, vB = 0.0f;
#pragma unroll
        for (int w = 0; w < 8; w++) { vA += sA[w][tid]; vB += sB[w][tid]; }
        vA += bias[row0 + tid];
        outA[row0 + tid] = vA;
        outB[row0 + tid] = vB;
    }
}

// enc L0 (256 MB, first in chain)
__global__ void __launch_bounds__(256) k_enc0(
    const float* __restrict__ W, const float* __restrict__ x,
    const float* __restrict__ dx, const float* __restrict__ b)
{
    pdl_trigger();
    const int row0 = blockIdx.x * 4;
    big_body<W0_IN, false>(W + (size_t)row0 * W0_IN, x, dx, b, g_pre1, g_u1, row0);
}

// dec L2 (256 MB, last)
__global__ void __launch_bounds__(256) k_dec2(
    const float* __restrict__ W, const float* __restrict__ b,
    float* __restrict__ out)
{
    const int row0 = blockIdx.x * 4;
    const float* Wt = W + (size_t)row0 * 4096;
    prefetch_tile<256>(Wt, 4 * 4096 * 4);   // overlap weight fetch with predecessor
    pdl_wait();
    big_body<4096, true>(Wt, g_q2, g_v2, b, out + 48, out + 48 + 16384, row0);
}

// ---------------------------------------------------------------------------
// Non-pipelined dual matvec for the 16MB kernels (R4-proven).
// ---------------------------------------------------------------------------
template<int KSTRIDE, int KCHUNK, int ROWS, int THREADS, bool SIG>
__device__ __forceinline__ void dual_body(
    const float* __restrict__ W,
    const float* __restrict__ av,
    const float* __restrict__ bv,
    const float* __restrict__ bias,
    float* __restrict__ outA,
    float* __restrict__ outB,
    int row0)
{
    constexpr int NW = THREADS / 32;
    constexpr int ITERS = KCHUNK / (THREADS * 4);
    const int tid = threadIdx.x;

    float accA[ROWS], accB[ROWS];
#pragma unroll
    for (int r = 0; r < ROWS; r++) { accA[r] = 0.0f; accB[r] = 0.0f; }

#pragma unroll 2
    for (int it = 0; it < ITERS; it++) {
        const int k = (it * THREADS + tid) * 4;
        float4 w4[ROWS];
#pragma unroll
        for (int r = 0; r < ROWS; r++)
            w4[r] = ldcs4(W + (size_t)r * KSTRIDE + k);
        float4 a4 = *(const float4*)(av + k);
        float4 b4 = *(const float4*)(bv + k);
        if (SIG) {
            float s;
            s = sigf(a4.x); b4.x *= s * (1.0f - s); a4.x = s;
            s = sigf(a4.y); b4.y *= s * (1.0f - s); a4.y = s;
            s = sigf(a4.z); b4.z *= s * (1.0f - s); a4.z = s;
            s = sigf(a4.w); b4.w *= s * (1.0f - s); a4.w = s;
        }
#pragma unroll
        for (int r = 0; r < ROWS; r++) {
            accA[r] = fmaf(w4[r].x, a4.x, accA[r]);
            accA[r] = fmaf(w4[r].y, a4.y, accA[r]);
            accA[r] = fmaf(w4[r].z, a4.z, accA[r]);
            accA[r] = fmaf(w4[r].w, a4.w, accA[r]);
            accB[r] = fmaf(w4[r].x, b4.x, accB[r]);
            accB[r] = fmaf(w4[r].y, b4.y, accB[r]);
            accB[r] = fmaf(w4[r].z, b4.z, accB[r]);
            accB[r] = fmaf(w4[r].w, b4.w, accB[r]);
        }
    }

    __shared__ float sA[NW][ROWS], sB[NW][ROWS];
    const int lane = tid & 31, warp = tid >> 5;
#pragma unroll
    for (int r = 0; r < ROWS; r++) {
        float vA = accA[r], vB = accB[r];
#pragma unroll
        for (int o = 16; o; o >>= 1) {
            vA += __shfl_xor_sync(0xffffffffu, vA, o);
            vB += __shfl_xor_sync(0xffffffffu, vB, o);
        }
        if (lane == 0) { sA[warp][r] = vA; sB[warp][r] = vB; }
    }
    __syncthreads();
    if (tid < ROWS) {
        float vA = 0.0f, vB = 0.0f;
#pragma unroll
        for (int w = 0; w < NW; w++) { vA += sA[w][tid]; vB += sB[w][tid]; }
        if (bias) vA += bias[row0 + tid];
        outA[row0 + tid] = vA;
        outB[row0 + tid] = vB;
    }
}

// enc L1, split-K x2 (16 MB)
__global__ void __launch_bounds__(256) k_enc1(
    const float* __restrict__ W, const float* __restrict__ b)
{
    pdl_trigger();
    const int row0  = blockIdx.x * 4;
    const int split = blockIdx.y;
    const int koff  = split * 2048;
    const float* Wt = W + (size_t)row0 * W0_OUT + koff;
#pragma unroll
    for (int r = 0; r < 4; r++)
        prefetch_tile<256>(Wt + (size_t)r * W0_OUT, 8192);
    pdl_wait();
    dual_body<W0_OUT, 2048, 4, 256, true>(
        Wt, g_pre1 + koff, g_u1 + koff,
        split == 0 ? b : nullptr,
        g_pre2p + split * W1_OUT, g_u2p + split * W1_OUT, row0);
}

// dec L1 (16 MB)
__global__ void __launch_bounds__(256) k_dec1(
    const float* __restrict__ W, const float* __restrict__ b)
{
    pdl_trigger();
    const int row0 = blockIdx.x * 4;
    const float* Wt = W + (size_t)row0 * 1024;
    prefetch_tile<256>(Wt, 4 * 1024 * 4);
    pdl_wait();
    dual_body<1024, 1024, 4, 256, false>(
        Wt, g_g1, g_p1, b, g_q2, g_v2, row0);
}

// ---------------------------------------------------------------------------
// Middle chain, one block, 512 threads, weights prefetched to smem (R4).
// ---------------------------------------------------------------------------
#define SM_WE2   0
#define SM_EW    16384
#define SM_WD0   32128
#define SM_H2    48512
#define SM_T2    49536
#define SM_THETA 50560
#define SM_FLOATS 51544
#define SM_BYTES (SM_FLOATS * 4)

__global__ void __launch_bounds__(512) k_small(
    const float* __restrict__ we_w2, const float* __restrict__ we_b2,
    const float* __restrict__ E_w,   const float* __restrict__ E_b,
    const float* __restrict__ wd_w0, const float* __restrict__ wd_b0,
    float* __restrict__ out)
{
    extern __shared__ float sm[];
    __shared__ float z[LATENT], dz[LATENT], dzb[LATENT];

    const int tid = threadIdx.x;
    const int lane = tid & 31, wid = tid >> 5;

    pdl_trigger();
    prefetch_tile<512>(we_w2, 16384 * 4);
    prefetch_tile<512>(E_w,   15744 * 4);
    prefetch_tile<512>(wd_w0, 16384 * 4);
    pdl_wait();

    for (int i = tid; i < 4096; i += 512)
        *(float4*)(sm + SM_WE2 + i * 4) = ldcs4(we_w2 + i * 4);
    for (int i = tid; i < 3936; i += 512)
        *(float4*)(sm + SM_EW + i * 4) = ldcs4(E_w + i * 4);
    for (int i = tid; i < 4096; i += 512)
        *(float4*)(sm + SM_WD0 + i * 4) = ldcs4(wd_w0 + i * 4);
    for (int i = tid; i < W1_OUT; i += 512) {
        float pre = g_pre2p[i] + g_pre2p[W1_OUT + i];
        float u   = g_u2p[i]   + g_u2p[W1_OUT + i];
        float s = sigf(pre);
        sm[SM_H2 + i] = s;
        sm[SM_T2 + i] = s * (1.0f - s) * u;
    }
    __syncthreads();

    {
        float az = 0.0f, ad = 0.0f;
        const float* wr = sm + SM_WE2 + wid * W1_OUT;
        for (int c = lane; c < W1_OUT; c += 32) {
            float w = wr[c];
            az = fmaf(w, sm[SM_H2 + c], az);
            ad = fmaf(w, sm[SM_T2 + c], ad);
        }
#pragma unroll
        for (int o = 16; o; o >>= 1) {
            az += __shfl_xor_sync(0xffffffffu, az, o);
            ad += __shfl_xor_sync(0xffffffffu, ad, o);
        }
        if (lane == 0) { z[wid] = az + we_b2[wid]; dz[wid] = ad; }
    }
    __syncthreads();

    if (tid < LATENT) { out[tid] = z[tid]; out[LATENT + tid] = dz[tid]; }

    for (int idx = tid; idx < SINDY_DIM; idx += 512) {
        float v;
        if (idx < 16) v = 1.0f;
        else if (idx < 32) v = z[idx - 16];
        else if (idx < 168) {
            int q = idx - 32, i = 0;
            for (;;) { int m = 16 - i; if (q < m) break; q -= m; i++; }
            v = z[i] * z[i + q];
        } else {
            int t = idx - 168, i = 0;
            for (;;) { int m = 16 - i; int c = m * (m + 1) / 2; if (t < c) break; t -= c; i++; }
            int j = i;
            for (;;) { int m = 16 - j; if (t < m) break; t -= m; j++; }
            v = z[i] * z[j] * z[j + t];
        }
        sm[SM_THETA + idx] = v;
    }
    __syncthreads();

    {
        float a = 0.0f;
        const float* er = sm + SM_EW + wid * SINDY_DIM;
        for (int c = lane; c < SINDY_DIM; c += 32)
            a = fmaf(er[c], sm[SM_THETA + c], a);
#pragma unroll
        for (int o = 16; o; o >>= 1)
            a += __shfl_xor_sync(0xffffffffu, a, o);
        if (lane == 0) dzb[wid] = a + E_b[wid];
    }
    __syncthreads();

    if (tid < LATENT) out[32 + tid] = dzb[tid];

    for (int row = tid; row < 1024; row += 512) {
        float a = wd_b0[row], bb = 0.0f;
        const float* wr = sm + SM_WD0 + row * LATENT;
#pragma unroll
        for (int c = 0; c < LATENT; c++) {
            float w = wr[c];
            a  = fmaf(w, z[c],   a);
            bb = fmaf(w, dzb[c], bb);
        }
        float s = sigf(a);
        g_g1[row] = s;
        g_p1[row] = s * (1.0f - s) * bb;
    }
}

// ---------------------------------------------------------------------------
extern "C" void kernel_launch(void* const* d_in, const int* in_sizes, int n_in,
                              void* d_out, int out_size)
{
    const float* x     = (const float*)d_in[0];
    const float* dx    = (const float*)d_in[1];
    const float* we_w0 = (const float*)d_in[3];
    const float* we_b0 = (const float*)d_in[4];
    const float* we_w1 = (const float*)d_in[5];
    const float* we_b1 = (const float*)d_in[6];
    const float* we_w2 = (const float*)d_in[7];
    const float* we_b2 = (const float*)d_in[8];
    const float* wd_w0 = (const float*)d_in[9];
    const float* wd_b0 = (const float*)d_in[10];
    const float* wd_w1 = (const float*)d_in[11];
    const float* wd_b1 = (const float*)d_in[12];
    const float* wd_w2 = (const float*)d_in[13];
    const float* wd_b2 = (const float*)d_in[14];
    const float* E_w   = (const float*)d_in[15];
    const float* E_b   = (const float*)d_in[16];
    float* out = (float*)d_out;

    cudaFuncSetAttribute(k_small, cudaFuncAttributeMaxDynamicSharedMemorySize, SM_BYTES);
    cudaFuncSetAttribute(k_enc0,  cudaFuncAttributeMaxDynamicSharedMemorySize, BIG_SM_BYTES);
    cudaFuncSetAttribute(k_dec2,  cudaFuncAttributeMaxDynamicSharedMemorySize, BIG_SM_BYTES);

    cudaLaunchAttribute attr[1];
    attr[0].id = cudaLaunchAttributeProgrammaticStreamSerialization;
    attr[0].val.programmaticStreamSerializationAllowed = 1;

    cudaLaunchConfig_t cfg{};
    cfg.blockDim = dim3(256, 1, 1);
    cfg.dynamicSmemBytes = 0;
    cfg.stream = 0;
    cfg.attrs = attr;
    cfg.numAttrs = 1;

    // 1) enc L0 (256 MB)
    cfg.gridDim = dim3(W0_OUT / 4, 1, 1);
    cfg.dynamicSmemBytes = BIG_SM_BYTES;
    cudaLaunchKernelEx(&cfg, k_enc0, we_w0, x, dx, we_b0);
    cfg.dynamicSmemBytes = 0;

    // 2) enc L1 (16 MB, split-K x2)
    cfg.gridDim = dim3(W1_OUT / 4, 2, 1);
    cudaLaunchKernelEx(&cfg, k_enc1, we_w1, we_b1);

    // 3) middle chain
    {
        cudaLaunchConfig_t cs = cfg;
        cs.gridDim = dim3(1, 1, 1);
        cs.blockDim = dim3(512, 1, 1);
        cs.dynamicSmemBytes = SM_BYTES;
        cudaLaunchKernelEx(&cs, k_small, we_w2, we_b2, E_w, E_b, wd_w0, wd_b0, out);
    }

    // 4) dec L1 (16 MB)
    cfg.gridDim = dim3(4096 / 4, 1, 1);
    cudaLaunchKernelEx(&cfg, k_dec1, wd_w1, wd_b1);

    // 5) dec L2 (256 MB)
    cfg.gridDim = dim3(16384 / 4, 1, 1);
    cfg.dynamicSmemBytes = BIG_SM_BYTES;
    cudaLaunchKernelEx(&cfg, k_dec2, wd_w2, wd_b2, out);
}